// round 4
// baseline (speedup 1.0000x reference)
#include <cuda_runtime.h>
#include <math.h>

#define NMAX  12288
#define SEG   1536            // NMAX / NSEG
#define NSEG  8
#define QB    128             // threads per block
#define QBLK  (SEG / QB)      // 12 query windows per segment
#define NQB   (NSEG * QBLK)   // 96 query windows total
#define NB    384             // persistent blocks (all co-resident; see launch_bounds)
#define EPT   (SEG / QB)      // 12 elements per thread in segment scan
#define SBLK  (NMAX / QB)     // 96 strain blocks (1 point per thread)

struct CMat { float m[9]; float s; };

// ---- persistent scratch (zero-init at load; re-armed every replay) ----
__device__ float4 g_cand[NMAX];                 // compacted {x,y,z,|w|^2}; padded BIG
__device__ int    g_cidx[NMAX];                 // compact slot -> original index
__device__ int    g_cnt[NSEG];
__device__ unsigned long long g_best[NMAX];     // ~((ord(d)<<32)|orig_j); 0 = armed
__device__ double g_bsum[SBLK];
__device__ int    g_bcnt[SBLK];
__device__ int    g_c1, g_c2, g_c3;             // barrier / ticket counters

__device__ __forceinline__ unsigned int ford(float f) {
    unsigned int u = __float_as_uint(f);
    return (u & 0x80000000u) ? ~u : (u | 0x80000000u);
}
__device__ __forceinline__ float finv(unsigned int o) {
    unsigned int u = (o & 0x80000000u) ? (o ^ 0x80000000u) : ~o;
    return __uint_as_float(u);
}

__device__ __forceinline__ void grid_barrier(int* ctr, int target) {
    __syncthreads();
    if (threadIdx.x == 0) {
        __threadfence();
        atomicAdd(ctr, 1);
        while (atomicAdd(ctr, 0) < target) __nanosleep(64);
    }
    __syncthreads();
    __threadfence();
}

// ============================================================
// One persistent kernel: compact -> barrier -> NN -> barrier -> strain+reduce
// ============================================================
__global__ void __launch_bounds__(QB, 4) k_all(const float* __restrict__ new_xyz,
                                               const float* __restrict__ xyz,
                                               const float* __restrict__ gt_sdf,
                                               CMat C, float* __restrict__ out) {
    __shared__ float4 tile[SEG];          // 24 KB
    __shared__ int    s_cor[SEG];         // 6 KB
    __shared__ int    s_w[4];
    __shared__ double s_rd[QB];
    __shared__ int    s_ri[QB];
    __shared__ int    s_last;

    int tid = threadIdx.x, lane = tid & 31, wid = tid >> 5;
    int b   = blockIdx.x;

    // ---------------- Phase 0: compaction (blocks 0..NSEG-1) ----------------
    if (b < NSEG) {
        int s0 = b * SEG;
        const float4* ps = (const float4*)(gt_sdf + s0 + EPT * tid);
        float4 a = ps[0], bb = ps[1], cc = ps[2];
        float v[12] = {a.x,a.y,a.z,a.w, bb.x,bb.y,bb.z,bb.w, cc.x,cc.y,cc.z,cc.w};
        unsigned fl = 0; int myc = 0;
        #pragma unroll
        for (int e = 0; e < 12; ++e) if (v[e] < 1e-8f) { fl |= 1u << e; myc++; }
        int pre = myc;
        #pragma unroll
        for (int o = 1; o < 32; o <<= 1) { int t2 = __shfl_up_sync(~0u, pre, o); if (lane >= o) pre += t2; }
        if (lane == 31) s_w[wid] = pre;
        __syncthreads();
        int woff = 0;
        #pragma unroll
        for (int w = 0; w < 4; ++w) if (w < wid) woff += s_w[w];
        int pos = woff + pre - myc;                       // exclusive prefix in segment
        int cnt = s_w[0] + s_w[1] + s_w[2] + s_w[3];
        #pragma unroll
        for (int e = 0; e < 12; ++e) {
            if (fl & (1u << e)) {
                int idx = s0 + EPT * tid + e;
                float x = new_xyz[3 * idx + 0];
                float y = new_xyz[3 * idx + 1];
                float z = new_xyz[3 * idx + 2];
                g_cand[s0 + pos] = make_float4(x, y, z, x * x + y * y + z * z);
                g_cidx[s0 + pos] = idx;
                pos++;
            }
        }
        for (int p = cnt + tid; p < SEG; p += QB)
            g_cand[s0 + p] = make_float4(0.f, 0.f, 0.f, 1e30f);
        if (tid == 0) g_cnt[b] = cnt;
    }

    grid_barrier(&g_c1, NB);

    // ---------------- Phase 1: NN (2 work items per block, same qb) ----------
    int qb   = b % NQB;                                   // 0..95
    int qseg = qb / QBLK;
    int qw0  = (qb % QBLK) * QB;
    int cntq = g_cnt[qseg];

    if (qw0 < cntq) {                                     // block-uniform activity
        int ql = qw0 + tid;
        bool qa = (ql < cntq);
        float4 wq = g_cand[qseg * SEG + min(ql, SEG - 1)];
        int qorig = qa ? g_cidx[qseg * SEG + ql] : 0;
        float ax = -2.f * wq.x, ay = -2.f * wq.y, az = -2.f * wq.z;

        #pragma unroll
        for (int r = 0; r < 2; ++r) {
            int csp  = (b / NQB) + 4 * r;                 // 0..7, each (qb,csp) once
            int cntc = g_cnt[csp];
            if (r) __syncthreads();                       // protect tile reuse
            for (int k = tid; k < cntc; k += QB) {
                tile[k]  = g_cand[csp * SEG + k];
                s_cor[k] = g_cidx[csp * SEG + k];
            }
            __syncthreads();

            float best = 3.0e38f;
            int   bc   = 0;
            if (csp != qseg) {
                #pragma unroll 8
                for (int k = 0; k < cntc; ++k) {
                    float4 c = tile[k];
                    float d = fmaf(c.x, ax, fmaf(c.y, ay, fmaf(c.z, az, c.w)));
                    if (d < best) { best = d; bc = k; }
                }
            } else {
                int sk = ql;
                #pragma unroll 8
                for (int k = 0; k < cntc; ++k) {
                    float4 c = tile[k];
                    float d = fmaf(c.x, ax, fmaf(c.y, ay, fmaf(c.z, az, c.w)));
                    if (d < best && k != sk) { best = d; bc = k; }
                }
            }
            if (qa && cntc > 0) {
                unsigned long long key =
                    ((unsigned long long)ford(best) << 32) | (unsigned int)s_cor[bc];
                atomicMax(&g_best[qorig], ~key);          // max(~key) == min(key)
            }
        }
    }

    grid_barrier(&g_c2, NB);

    // ---------------- Phase 2: strain + reduction (blocks 0..SBLK-1) ---------
    if (b >= SBLK) return;

    int i = b * QB + tid;                                 // original point index
    double qsq = 0.0;
    int cnt = 0;
    unsigned long long kp = g_best[i];
    g_best[i] = 0ULL;                                     // re-arm for next replay
    if (kp != 0ULL && gt_sdf[i] < 1e-8f) {
        unsigned long long key = ~kp;
        float deff = finv((unsigned int)(key >> 32));
        int   nn   = (int)(unsigned int)(key & 0xffffffffu);
        float wqx = new_xyz[3 * i + 0], wqy = new_xyz[3 * i + 1], wqz = new_xyz[3 * i + 2];
        float sqi = wqx * wqx + wqy * wqy + wqz * wqz;
        float mind2 = deff + sqi;                         // add back sq_i
        if (mind2 > 1e-16f) {                             // inside & (nn_d > 1e-8)
            cnt = 1;
            float wnx = new_xyz[3 * nn + 0], wny = new_xyz[3 * nn + 1], wnz = new_xyz[3 * nn + 2];
            float xi0 = xyz[3 * i + 0],  xi1 = xyz[3 * i + 1],  xi2 = xyz[3 * i + 2];
            float xn0 = xyz[3 * nn + 0], xn1 = xyz[3 * nn + 1], xn2 = xyz[3 * nn + 2];
            float du = (wnx - xn0) - (wqx - xi0);         // dm = motion[nn] - motion[i]
            float dv = (wny - xn1) - (wqy - xi1);
            float dw = (wnz - xn2) - (wqz - xi2);
            float dx = wnx - wqx + 1e-8f;
            float dy = wny - wqy + 1e-8f;
            float dz = wnz - wqz + 1e-8f;
            float e0 = du / dx, e1 = dv / dy, e2 = dw / dz;
            float e3 = (du / dy + dv / dx) * 0.5f;
            float e4 = (du / dz + dw / dx) * 0.5f;
            float e5 = (dw / dy + dv / dz) * 0.5f;
            float r0 = C.m[0] * e0 + C.m[1] * e1 + C.m[2] * e2;
            float r1 = C.m[3] * e0 + C.m[4] * e1 + C.m[5] * e2;
            float r2 = C.m[6] * e0 + C.m[7] * e1 + C.m[8] * e2;
            float q  = e0 * r0 + e1 * r1 + e2 * r2
                     + C.s * (e3 * e3 + e4 * e4 + e5 * e5);
            qsq = (double)q * (double)q;
        }
    }
    s_rd[tid] = qsq;
    s_ri[tid] = cnt;
    __syncthreads();
    #pragma unroll
    for (int o = QB / 2; o > 0; o >>= 1) {                // deterministic tree
        if (tid < o) { s_rd[tid] += s_rd[tid + o]; s_ri[tid] += s_ri[tid + o]; }
        __syncthreads();
    }
    if (tid == 0) {
        g_bsum[b] = s_rd[0];
        g_bcnt[b] = s_ri[0];
        __threadfence();
        int v = atomicAdd(&g_c3, 1);
        s_last = (v == SBLK - 1);
    }
    __syncthreads();

    if (s_last) {                                         // last block: fixed-order final
        __threadfence();
        double s = 0.0; int c = 0;
        if (tid < SBLK) { s = g_bsum[tid]; c = g_bcnt[tid]; }
        s_rd[tid] = s; s_ri[tid] = c;
        __syncthreads();
        #pragma unroll
        for (int o = QB / 2; o > 0; o >>= 1) {
            if (tid < o) { s_rd[tid] += s_rd[tid + o]; s_ri[tid] += s_ri[tid + o]; }
            __syncthreads();
        }
        if (tid == 0) {
            out[0] = (float)(sqrt(s_rd[0]) / (double)s_ri[0]);
            g_c1 = 0; g_c2 = 0; g_c3 = 0;                 // reset for next replay
        }
    }
}

// ============================================================
extern "C" void kernel_launch(void* const* d_in, const int* in_sizes, int n_in,
                              void* d_out, int out_size) {
    const float* new_xyz = (const float*)d_in[0];
    const float* xyz     = (const float*)d_in[1];
    const float* gt_sdf  = (const float*)d_in[2];

    CMat C;
    {
        const double EP = 0.21, VP = 0.4;
        double A[3][3] = {{1.0/EP, -VP/EP, -VP/EP},
                          {-VP/EP, 1.0/EP, -VP/EP},
                          {-VP,    -VP,    1.0/EP}};
        double det = A[0][0]*(A[1][1]*A[2][2]-A[1][2]*A[2][1])
                   - A[0][1]*(A[1][0]*A[2][2]-A[1][2]*A[2][0])
                   + A[0][2]*(A[1][0]*A[2][1]-A[1][1]*A[2][0]);
        double inv[3][3];
        inv[0][0] = (A[1][1]*A[2][2]-A[1][2]*A[2][1])/det;
        inv[0][1] = (A[0][2]*A[2][1]-A[0][1]*A[2][2])/det;
        inv[0][2] = (A[0][1]*A[1][2]-A[0][2]*A[1][1])/det;
        inv[1][0] = (A[1][2]*A[2][0]-A[1][0]*A[2][2])/det;
        inv[1][1] = (A[0][0]*A[2][2]-A[0][2]*A[2][0])/det;
        inv[1][2] = (A[0][2]*A[1][0]-A[0][0]*A[1][2])/det;
        inv[2][0] = (A[1][0]*A[2][1]-A[1][1]*A[2][0])/det;
        inv[2][1] = (A[0][1]*A[2][0]-A[0][0]*A[2][1])/det;
        inv[2][2] = (A[0][0]*A[1][1]-A[0][1]*A[1][0])/det;
        for (int i = 0; i < 3; i++)
            for (int j = 0; j < 3; j++)
                C.m[i * 3 + j] = (float)inv[i][j];
        C.s = (float)(EP / (2.0 * (1.0 + VP)));
    }

    k_all<<<NB, QB>>>(new_xyz, xyz, gt_sdf, C, (float*)d_out);
}

// round 5
// speedup vs baseline: 1.1148x; 1.1148x over previous
#include <cuda_runtime.h>
#include <math.h>

#define NMAX  12288
#define SEG   1536            // NMAX / NSEG
#define NSEG  8
#define QB    128             // threads per block
#define QBLK  (SEG / QB)      // 12 query windows per segment
#define NQB   (NSEG * QBLK)   // 96 query windows
#define NB    768             // persistent blocks, all co-resident (6/SM x 148 = 888 cap)
#define EPT   (SEG / QB)      // 12 elements/thread in segment scan
#define SBLK  (NMAX / QB)     // 96 strain blocks
#define HSEG  ((SEG / 2) + 4) // half-segment tile capacity (+pad)

struct CMat { float m[9]; float s; };

// ---- persistent scratch (zero-init at load; monotone counters, no resets) ----
__device__ float4 g_cand[NMAX];                 // compacted {x,y,z,|w|^2}; padded BIG
__device__ int    g_cidx[NMAX];                 // compact slot -> original index
__device__ int    g_cnt[NSEG];
__device__ unsigned long long g_best[NMAX];     // ~((ord(d)<<32)|orig_j); 0 = armed
__device__ double g_bsum[SBLK];
__device__ int    g_bcnt[SBLK];
__device__ unsigned int g_c1, g_c2, g_c3;       // monotone barrier/ticket counters

__device__ __forceinline__ unsigned int ford(float f) {
    unsigned int u = __float_as_uint(f);
    return (u & 0x80000000u) ? ~u : (u | 0x80000000u);
}
__device__ __forceinline__ float finv(unsigned int o) {
    unsigned int u = (o & 0x80000000u) ? (o ^ 0x80000000u) : ~o;
    return __uint_as_float(u);
}

// monotone grid barrier: counter never resets, so no stale-spinner hazard
// across graph replays (replays are stream-serialized, so per-replay cohorts
// occupy disjoint [r*NB, (r+1)*NB) ranges).
__device__ __forceinline__ void gbar(unsigned int* ctr) {
    __syncthreads();
    if (threadIdx.x == 0) {
        __threadfence();
        unsigned int v = atomicAdd(ctr, 1u);
        unsigned int target = (v / NB + 1u) * NB;
        while (*(volatile unsigned int*)ctr < target) __nanosleep(32);
        __threadfence();
    }
    __syncthreads();
}

// ============================================================
// One persistent kernel: compact -> gbar -> NN (ILP-4) -> gbar -> strain+reduce
// ============================================================
__global__ void __launch_bounds__(QB, 6) k_all(const float* __restrict__ new_xyz,
                                               const float* __restrict__ xyz,
                                               const float* __restrict__ gt_sdf,
                                               CMat C, float* __restrict__ out) {
    __shared__ float4 tile[HSEG];         // 12.3 KB
    __shared__ int    s_cor[HSEG];        // 3.1 KB
    __shared__ int    s_w[4];
    __shared__ double s_rd[QB];
    __shared__ int    s_ri[QB];
    __shared__ int    s_last;

    int tid = threadIdx.x, lane = tid & 31, wid = tid >> 5;
    int b   = blockIdx.x;

    // ---------------- Phase 0: compaction (blocks 0..7) ----------------
    if (b < NSEG) {
        int s0 = b * SEG;
        const float4* ps = (const float4*)(gt_sdf + s0 + EPT * tid);
        float4 a = ps[0], bb = ps[1], cc = ps[2];
        float v[12] = {a.x,a.y,a.z,a.w, bb.x,bb.y,bb.z,bb.w, cc.x,cc.y,cc.z,cc.w};
        unsigned fl = 0; int myc = 0;
        #pragma unroll
        for (int e = 0; e < 12; ++e) if (v[e] < 1e-8f) { fl |= 1u << e; myc++; }
        int pre = myc;
        #pragma unroll
        for (int o = 1; o < 32; o <<= 1) { int t2 = __shfl_up_sync(~0u, pre, o); if (lane >= o) pre += t2; }
        if (lane == 31) s_w[wid] = pre;
        __syncthreads();
        int woff = 0;
        #pragma unroll
        for (int w = 0; w < 4; ++w) if (w < wid) woff += s_w[w];
        int pos = woff + pre - myc;
        int cnt = s_w[0] + s_w[1] + s_w[2] + s_w[3];
        #pragma unroll
        for (int e = 0; e < 12; ++e) {
            if (fl & (1u << e)) {
                int idx = s0 + EPT * tid + e;
                float x = new_xyz[3 * idx + 0];
                float y = new_xyz[3 * idx + 1];
                float z = new_xyz[3 * idx + 2];
                g_cand[s0 + pos] = make_float4(x, y, z, x * x + y * y + z * z);
                g_cidx[s0 + pos] = idx;
                pos++;
            }
        }
        for (int p = cnt + tid; p < SEG; p += QB)
            g_cand[s0 + p] = make_float4(0.f, 0.f, 0.f, 1e30f);
        if (tid == 0) g_cnt[b] = cnt;
    }

    gbar(&g_c1);

    // ---------------- Phase 1: NN ----------------
    // block b: query window qb = b % 96, candidate segment cs = b / 96 (0..7),
    // scanned in two balanced halves; one atomic per (query, segment).
    {
        int qb   = b % NQB;
        int cs   = b / NQB;
        int qseg = qb / QBLK;
        int qw0  = (qb % QBLK) * QB;
        int cntq = g_cnt[qseg];

        if (qw0 < cntq) {                                 // block-uniform
            int ql = qw0 + tid;
            bool qa = (ql < cntq);
            float4 wq = g_cand[qseg * SEG + min(ql, SEG - 1)];
            int qorig = qa ? g_cidx[qseg * SEG + ql] : 0;
            float ax = -2.f * wq.x, ay = -2.f * wq.y, az = -2.f * wq.z;

            int cntseg = g_cnt[cs];
            int half0  = (cntseg + 1) >> 1;
            bool selfseg = (cs == qseg);                  // block-uniform
            unsigned long long bkey = 0xffffffffffffffffULL;

            #pragma unroll
            for (int r = 0; r < 2; ++r) {
                int off  = r ? half0 : 0;
                int cntc = r ? (cntseg - half0) : half0;
                if (r) __syncthreads();                   // tile reuse
                for (int k = tid; k < cntc; k += QB) {
                    tile[k]  = g_cand[cs * SEG + off + k];
                    s_cor[k] = g_cidx[cs * SEG + off + k];
                }
                int cntc4 = (cntc + 3) & ~3;
                if (tid < cntc4 - cntc) {                 // pad (<=3 slots)
                    tile[cntc + tid]  = make_float4(0.f, 0.f, 0.f, 1e30f);
                    s_cor[cntc + tid] = 0;
                }
                __syncthreads();
                if (cntc <= 0) continue;

                // 4 independent accumulators -> 4x shorter FSETP chain
                float b0 = 3e38f, b1 = 3e38f, b2 = 3e38f, b3 = 3e38f;
                int   i0 = 0, i1 = 1, i2 = 2, i3 = 3;
                if (!selfseg) {
                    #pragma unroll 2
                    for (int k = 0; k < cntc4; k += 4) {
                        float4 c0 = tile[k],     c1 = tile[k + 1];
                        float4 c2 = tile[k + 2], c3 = tile[k + 3];
                        float d0 = fmaf(c0.x, ax, fmaf(c0.y, ay, fmaf(c0.z, az, c0.w)));
                        float d1 = fmaf(c1.x, ax, fmaf(c1.y, ay, fmaf(c1.z, az, c1.w)));
                        float d2 = fmaf(c2.x, ax, fmaf(c2.y, ay, fmaf(c2.z, az, c2.w)));
                        float d3 = fmaf(c3.x, ax, fmaf(c3.y, ay, fmaf(c3.z, az, c3.w)));
                        if (d0 < b0) { b0 = d0; i0 = k; }
                        if (d1 < b1) { b1 = d1; i1 = k + 1; }
                        if (d2 < b2) { b2 = d2; i2 = k + 2; }
                        if (d3 < b3) { b3 = d3; i3 = k + 3; }
                    }
                } else {
                    int sk = ql - off;                    // self slot (may be out of range: harmless)
                    #pragma unroll 2
                    for (int k = 0; k < cntc4; k += 4) {
                        float4 c0 = tile[k],     c1 = tile[k + 1];
                        float4 c2 = tile[k + 2], c3 = tile[k + 3];
                        float d0 = fmaf(c0.x, ax, fmaf(c0.y, ay, fmaf(c0.z, az, c0.w)));
                        float d1 = fmaf(c1.x, ax, fmaf(c1.y, ay, fmaf(c1.z, az, c1.w)));
                        float d2 = fmaf(c2.x, ax, fmaf(c2.y, ay, fmaf(c2.z, az, c2.w)));
                        float d3 = fmaf(c3.x, ax, fmaf(c3.y, ay, fmaf(c3.z, az, c3.w)));
                        if (d0 < b0 && k + 0 != sk) { b0 = d0; i0 = k; }
                        if (d1 < b1 && k + 1 != sk) { b1 = d1; i1 = k + 1; }
                        if (d2 < b2 && k + 2 != sk) { b2 = d2; i2 = k + 2; }
                        if (d3 < b3 && k + 3 != sk) { b3 = d3; i3 = k + 3; }
                    }
                }
                // merge accumulators: lexicographic (d, slot) -> first occurrence
                float bb = b0; int bi = i0;
                if (b1 < bb || (b1 == bb && i1 < bi)) { bb = b1; bi = i1; }
                if (b2 < bb || (b2 == bb && i2 < bi)) { bb = b2; bi = i2; }
                if (b3 < bb || (b3 == bb && i3 < bi)) { bb = b3; bi = i3; }
                unsigned long long key =
                    ((unsigned long long)ford(bb) << 32) | (unsigned int)s_cor[bi];
                if (key < bkey) bkey = key;               // halves: lower orig wins ties
            }

            if (qa && bkey != 0xffffffffffffffffULL)
                atomicMax(&g_best[qorig], ~bkey);         // max(~key) == min(key)
        }
    }

    gbar(&g_c2);

    // ---------------- Phase 2: strain + reduction (blocks 0..95) ----------
    if (b >= SBLK) return;

    int i = b * QB + tid;
    double qsq = 0.0;
    int cnt = 0;
    unsigned long long kp = g_best[i];
    g_best[i] = 0ULL;                                     // re-arm for next replay
    if (kp != 0ULL && gt_sdf[i] < 1e-8f) {
        unsigned long long key = ~kp;
        float deff = finv((unsigned int)(key >> 32));
        int   nn   = (int)(unsigned int)(key & 0xffffffffu);
        float wqx = new_xyz[3 * i + 0], wqy = new_xyz[3 * i + 1], wqz = new_xyz[3 * i + 2];
        float sqi = wqx * wqx + wqy * wqy + wqz * wqz;
        float mind2 = deff + sqi;
        if (mind2 > 1e-16f) {
            cnt = 1;
            float wnx = new_xyz[3 * nn + 0], wny = new_xyz[3 * nn + 1], wnz = new_xyz[3 * nn + 2];
            float xi0 = xyz[3 * i + 0],  xi1 = xyz[3 * i + 1],  xi2 = xyz[3 * i + 2];
            float xn0 = xyz[3 * nn + 0], xn1 = xyz[3 * nn + 1], xn2 = xyz[3 * nn + 2];
            float du = (wnx - xn0) - (wqx - xi0);
            float dv = (wny - xn1) - (wqy - xi1);
            float dw = (wnz - xn2) - (wqz - xi2);
            float dx = wnx - wqx + 1e-8f;
            float dy = wny - wqy + 1e-8f;
            float dz = wnz - wqz + 1e-8f;
            float e0 = du / dx, e1 = dv / dy, e2 = dw / dz;
            float e3 = (du / dy + dv / dx) * 0.5f;
            float e4 = (du / dz + dw / dx) * 0.5f;
            float e5 = (dw / dy + dv / dz) * 0.5f;
            float r0 = C.m[0] * e0 + C.m[1] * e1 + C.m[2] * e2;
            float r1 = C.m[3] * e0 + C.m[4] * e1 + C.m[5] * e2;
            float r2 = C.m[6] * e0 + C.m[7] * e1 + C.m[8] * e2;
            float q  = e0 * r0 + e1 * r1 + e2 * r2
                     + C.s * (e3 * e3 + e4 * e4 + e5 * e5);
            qsq = (double)q * (double)q;
        }
    }
    s_rd[tid] = qsq;
    s_ri[tid] = cnt;
    __syncthreads();
    #pragma unroll
    for (int o = QB / 2; o > 0; o >>= 1) {
        if (tid < o) { s_rd[tid] += s_rd[tid + o]; s_ri[tid] += s_ri[tid + o]; }
        __syncthreads();
    }
    if (tid == 0) {
        g_bsum[b] = s_rd[0];
        g_bcnt[b] = s_ri[0];
        __threadfence();
        unsigned int v = atomicAdd(&g_c3, 1u);
        s_last = ((v % SBLK) == SBLK - 1);                // monotone ticket
    }
    __syncthreads();

    if (s_last) {
        __threadfence();
        double s = 0.0; int c = 0;
        if (tid < SBLK) { s = g_bsum[tid]; c = g_bcnt[tid]; }
        s_rd[tid] = s; s_ri[tid] = c;
        __syncthreads();
        #pragma unroll
        for (int o = QB / 2; o > 0; o >>= 1) {
            if (tid < o) { s_rd[tid] += s_rd[tid + o]; s_ri[tid] += s_ri[tid + o]; }
            __syncthreads();
        }
        if (tid == 0)
            out[0] = (float)(sqrt(s_rd[0]) / (double)s_ri[0]);
    }
}

// ============================================================
extern "C" void kernel_launch(void* const* d_in, const int* in_sizes, int n_in,
                              void* d_out, int out_size) {
    const float* new_xyz = (const float*)d_in[0];
    const float* xyz     = (const float*)d_in[1];
    const float* gt_sdf  = (const float*)d_in[2];

    CMat C;
    {
        const double EP = 0.21, VP = 0.4;
        double A[3][3] = {{1.0/EP, -VP/EP, -VP/EP},
                          {-VP/EP, 1.0/EP, -VP/EP},
                          {-VP,    -VP,    1.0/EP}};
        double det = A[0][0]*(A[1][1]*A[2][2]-A[1][2]*A[2][1])
                   - A[0][1]*(A[1][0]*A[2][2]-A[1][2]*A[2][0])
                   + A[0][2]*(A[1][0]*A[2][1]-A[1][1]*A[2][0]);
        double inv[3][3];
        inv[0][0] = (A[1][1]*A[2][2]-A[1][2]*A[2][1])/det;
        inv[0][1] = (A[0][2]*A[2][1]-A[0][1]*A[2][2])/det;
        inv[0][2] = (A[0][1]*A[1][2]-A[0][2]*A[1][1])/det;
        inv[1][0] = (A[1][2]*A[2][0]-A[1][0]*A[2][2])/det;
        inv[1][1] = (A[0][0]*A[2][2]-A[0][2]*A[2][0])/det;
        inv[1][2] = (A[0][2]*A[1][0]-A[0][0]*A[1][2])/det;
        inv[2][0] = (A[1][0]*A[2][1]-A[1][1]*A[2][0])/det;
        inv[2][1] = (A[0][1]*A[2][0]-A[0][0]*A[2][1])/det;
        inv[2][2] = (A[0][0]*A[1][1]-A[0][1]*A[1][0])/det;
        for (int i = 0; i < 3; i++)
            for (int j = 0; j < 3; j++)
                C.m[i * 3 + j] = (float)inv[i][j];
        C.s = (float)(EP / (2.0 * (1.0 + VP)));
    }

    k_all<<<NB, QB>>>(new_xyz, xyz, gt_sdf, C, (float*)d_out);
}

// round 6
// speedup vs baseline: 1.3682x; 1.2274x over previous
#include <cuda_runtime.h>
#include <math.h>

#define NMAX  12288
#define SEG   1536            // NMAX / NSEG
#define NSEG  8
#define QB    128             // threads per block
#define NB    768             // persistent blocks, all co-resident (6/SM x 148 = 888 cap)
#define EPT   (SEG / QB)      // 12 elements/thread in segment scan
#define SBLK  (NMAX / QB)     // 96 strain blocks
#define HSEG  ((SEG / 2) + 4) // half-segment tile capacity (+pad)

struct CMat { float m[9]; float s; };

// ---- persistent scratch (zero-init at load; monotone counters, no resets) ----
__device__ float4 g_cand[NMAX];                 // compacted {x,y,z,|w|^2}; padded BIG
__device__ int    g_cidx[NMAX];                 // compact slot -> original index
__device__ int    g_cnt[NSEG];
__device__ unsigned long long g_best[NMAX];     // ~((ord(d)<<32)|orig_j); 0 = armed
__device__ double g_bsum[SBLK];
__device__ int    g_bcnt[SBLK];
__device__ unsigned int g_c1, g_c2, g_c3;       // monotone barrier/ticket counters

__device__ __forceinline__ unsigned int ford(float f) {
    unsigned int u = __float_as_uint(f);
    return (u & 0x80000000u) ? ~u : (u | 0x80000000u);
}
__device__ __forceinline__ float finv(unsigned int o) {
    unsigned int u = (o & 0x80000000u) ? (o ^ 0x80000000u) : ~o;
    return __uint_as_float(u);
}

// monotone grid barrier (no reset -> no stale-spinner hazard across replays)
__device__ __forceinline__ void gbar(unsigned int* ctr) {
    __syncthreads();
    if (threadIdx.x == 0) {
        __threadfence();
        unsigned int v = atomicAdd(ctr, 1u);
        unsigned int target = (v / NB + 1u) * NB;
        while (*(volatile unsigned int*)ctr < target) __nanosleep(32);
        __threadfence();
    }
    __syncthreads();
}

// ============================================================
// One persistent kernel: compact -> gbar -> NN over real work items -> gbar
// -> strain+reduce
// ============================================================
__global__ void __launch_bounds__(QB, 6) k_all(const float* __restrict__ new_xyz,
                                               const float* __restrict__ xyz,
                                               const float* __restrict__ gt_sdf,
                                               CMat C, float* __restrict__ out) {
    __shared__ float4 tile[HSEG];         // 12.3 KB
    __shared__ int    s_cor[HSEG];        // 3.1 KB
    __shared__ int    s_w[4];
    __shared__ int    s_pw[NSEG + 1];     // window-count prefix over segments
    __shared__ int    s_cnt[NSEG];
    __shared__ double s_rd[QB];
    __shared__ int    s_ri[QB];
    __shared__ int    s_last;

    int tid = threadIdx.x, lane = tid & 31, wid = tid >> 5;
    int b   = blockIdx.x;

    // ---------------- Phase 0: compaction (blocks 0..7) ----------------
    if (b < NSEG) {
        int s0 = b * SEG;
        const float4* ps = (const float4*)(gt_sdf + s0 + EPT * tid);
        float4 a = ps[0], bb = ps[1], cc = ps[2];
        float v[12] = {a.x,a.y,a.z,a.w, bb.x,bb.y,bb.z,bb.w, cc.x,cc.y,cc.z,cc.w};
        unsigned fl = 0; int myc = 0;
        #pragma unroll
        for (int e = 0; e < 12; ++e) if (v[e] < 1e-8f) { fl |= 1u << e; myc++; }
        int pre = myc;
        #pragma unroll
        for (int o = 1; o < 32; o <<= 1) { int t2 = __shfl_up_sync(~0u, pre, o); if (lane >= o) pre += t2; }
        if (lane == 31) s_w[wid] = pre;
        __syncthreads();
        int woff = 0;
        #pragma unroll
        for (int w = 0; w < 4; ++w) if (w < wid) woff += s_w[w];
        int pos = woff + pre - myc;
        int cnt = s_w[0] + s_w[1] + s_w[2] + s_w[3];
        #pragma unroll
        for (int e = 0; e < 12; ++e) {
            if (fl & (1u << e)) {
                int idx = s0 + EPT * tid + e;
                float x = new_xyz[3 * idx + 0];
                float y = new_xyz[3 * idx + 1];
                float z = new_xyz[3 * idx + 2];
                g_cand[s0 + pos] = make_float4(x, y, z, x * x + y * y + z * z);
                g_cidx[s0 + pos] = idx;
                pos++;
            }
        }
        for (int p = cnt + tid; p < SEG; p += QB)
            g_cand[s0 + p] = make_float4(0.f, 0.f, 0.f, 1e30f);
        if (tid == 0) g_cnt[b] = cnt;
    }

    gbar(&g_c1);

    // ---------------- Phase 1: NN over dynamic work items ----------------
    // item = (active query window) x (candidate segment) x (half).
    if (tid < NSEG) s_cnt[tid] = g_cnt[tid];
    __syncthreads();
    if (tid == 0) {
        int acc = 0;
        #pragma unroll
        for (int s = 0; s < NSEG; ++s) {
            s_pw[s] = acc;
            acc += (s_cnt[s] + QB - 1) / QB;              // windows in segment s
        }
        s_pw[NSEG] = acc;
    }
    __syncthreads();
    int total = s_pw[NSEG] * NSEG * 2;

    for (int it = b; it < total; it += NB) {
        if (it != b) __syncthreads();                     // tile reuse guard
        int widx = it >> 4;                               // / (NSEG*2)
        int r    = it & 15;
        int cs   = r >> 1;
        int half = r & 1;
        int qseg = 0;
        #pragma unroll
        for (int s = 0; s < NSEG - 1; ++s) if (widx >= s_pw[s + 1]) qseg = s + 1;
        int qw0  = (widx - s_pw[qseg]) * QB;
        int cntq = s_cnt[qseg];

        int ql = qw0 + tid;
        bool qa = (ql < cntq);
        float4 wq = g_cand[qseg * SEG + min(ql, SEG - 1)];
        int qorig = qa ? g_cidx[qseg * SEG + ql] : 0;
        float ax = -2.f * wq.x, ay = -2.f * wq.y, az = -2.f * wq.z;

        int cntseg = s_cnt[cs];
        int half0  = (cntseg + 1) >> 1;
        int off    = half ? half0 : 0;
        int cntc   = half ? (cntseg - half0) : half0;
        bool selfseg = (cs == qseg);                      // block-uniform

        for (int k = tid; k < cntc; k += QB) {
            tile[k]  = g_cand[cs * SEG + off + k];
            s_cor[k] = g_cidx[cs * SEG + off + k];
        }
        int cntc4 = (cntc + 3) & ~3;
        if (tid < cntc4 - cntc) {                         // pad (<=3 slots)
            tile[cntc + tid]  = make_float4(0.f, 0.f, 0.f, 1e30f);
            s_cor[cntc + tid] = 0;
        }
        __syncthreads();
        if (cntc <= 0) continue;                          // block-uniform

        // 4 independent accumulators -> short dependency chains
        float b0 = 3e38f, b1 = 3e38f, b2 = 3e38f, b3 = 3e38f;
        int   i0 = 0, i1 = 1, i2 = 2, i3 = 3;
        if (!selfseg) {
            #pragma unroll 2
            for (int k = 0; k < cntc4; k += 4) {
                float4 c0 = tile[k],     c1 = tile[k + 1];
                float4 c2 = tile[k + 2], c3 = tile[k + 3];
                float d0 = fmaf(c0.x, ax, fmaf(c0.y, ay, fmaf(c0.z, az, c0.w)));
                float d1 = fmaf(c1.x, ax, fmaf(c1.y, ay, fmaf(c1.z, az, c1.w)));
                float d2 = fmaf(c2.x, ax, fmaf(c2.y, ay, fmaf(c2.z, az, c2.w)));
                float d3 = fmaf(c3.x, ax, fmaf(c3.y, ay, fmaf(c3.z, az, c3.w)));
                if (d0 < b0) { b0 = d0; i0 = k; }
                if (d1 < b1) { b1 = d1; i1 = k + 1; }
                if (d2 < b2) { b2 = d2; i2 = k + 2; }
                if (d3 < b3) { b3 = d3; i3 = k + 3; }
            }
        } else {
            int sk = ql - off;                            // self slot (may be out of range)
            #pragma unroll 2
            for (int k = 0; k < cntc4; k += 4) {
                float4 c0 = tile[k],     c1 = tile[k + 1];
                float4 c2 = tile[k + 2], c3 = tile[k + 3];
                float d0 = fmaf(c0.x, ax, fmaf(c0.y, ay, fmaf(c0.z, az, c0.w)));
                float d1 = fmaf(c1.x, ax, fmaf(c1.y, ay, fmaf(c1.z, az, c1.w)));
                float d2 = fmaf(c2.x, ax, fmaf(c2.y, ay, fmaf(c2.z, az, c2.w)));
                float d3 = fmaf(c3.x, ax, fmaf(c3.y, ay, fmaf(c3.z, az, c3.w)));
                if (d0 < b0 && k + 0 != sk) { b0 = d0; i0 = k; }
                if (d1 < b1 && k + 1 != sk) { b1 = d1; i1 = k + 1; }
                if (d2 < b2 && k + 2 != sk) { b2 = d2; i2 = k + 2; }
                if (d3 < b3 && k + 3 != sk) { b3 = d3; i3 = k + 3; }
            }
        }
        // merge accumulators: lexicographic (d, slot) -> first occurrence
        float bb = b0; int bi = i0;
        if (b1 < bb || (b1 == bb && i1 < bi)) { bb = b1; bi = i1; }
        if (b2 < bb || (b2 == bb && i2 < bi)) { bb = b2; bi = i2; }
        if (b3 < bb || (b3 == bb && i3 < bi)) { bb = b3; bi = i3; }

        if (qa) {
            unsigned long long key =
                ((unsigned long long)ford(bb) << 32) | (unsigned int)s_cor[bi];
            atomicMax(&g_best[qorig], ~key);              // max(~key) == min(key)
        }
    }

    gbar(&g_c2);

    // ---------------- Phase 2: strain + reduction (blocks 0..95) ----------
    if (b >= SBLK) return;

    int i = b * QB + tid;
    double qsq = 0.0;
    int cnt = 0;
    unsigned long long kp = g_best[i];
    g_best[i] = 0ULL;                                     // re-arm for next replay
    if (kp != 0ULL && gt_sdf[i] < 1e-8f) {
        unsigned long long key = ~kp;
        float deff = finv((unsigned int)(key >> 32));
        int   nn   = (int)(unsigned int)(key & 0xffffffffu);
        float wqx = new_xyz[3 * i + 0], wqy = new_xyz[3 * i + 1], wqz = new_xyz[3 * i + 2];
        float sqi = wqx * wqx + wqy * wqy + wqz * wqz;
        float mind2 = deff + sqi;
        if (mind2 > 1e-16f) {
            cnt = 1;
            float wnx = new_xyz[3 * nn + 0], wny = new_xyz[3 * nn + 1], wnz = new_xyz[3 * nn + 2];
            float xi0 = xyz[3 * i + 0],  xi1 = xyz[3 * i + 1],  xi2 = xyz[3 * i + 2];
            float xn0 = xyz[3 * nn + 0], xn1 = xyz[3 * nn + 1], xn2 = xyz[3 * nn + 2];
            float du = (wnx - xn0) - (wqx - xi0);
            float dv = (wny - xn1) - (wqy - xi1);
            float dw = (wnz - xn2) - (wqz - xi2);
            float dx = wnx - wqx + 1e-8f;
            float dy = wny - wqy + 1e-8f;
            float dz = wnz - wqz + 1e-8f;
            float e0 = du / dx, e1 = dv / dy, e2 = dw / dz;
            float e3 = (du / dy + dv / dx) * 0.5f;
            float e4 = (du / dz + dw / dx) * 0.5f;
            float e5 = (dw / dy + dv / dz) * 0.5f;
            float r0 = C.m[0] * e0 + C.m[1] * e1 + C.m[2] * e2;
            float r1 = C.m[3] * e0 + C.m[4] * e1 + C.m[5] * e2;
            float r2 = C.m[6] * e0 + C.m[7] * e1 + C.m[8] * e2;
            float q  = e0 * r0 + e1 * r1 + e2 * r2
                     + C.s * (e3 * e3 + e4 * e4 + e5 * e5);
            qsq = (double)q * (double)q;
        }
    }
    s_rd[tid] = qsq;
    s_ri[tid] = cnt;
    __syncthreads();
    #pragma unroll
    for (int o = QB / 2; o > 0; o >>= 1) {
        if (tid < o) { s_rd[tid] += s_rd[tid + o]; s_ri[tid] += s_ri[tid + o]; }
        __syncthreads();
    }
    if (tid == 0) {
        g_bsum[b] = s_rd[0];
        g_bcnt[b] = s_ri[0];
        __threadfence();
        unsigned int v = atomicAdd(&g_c3, 1u);
        s_last = ((v % SBLK) == SBLK - 1);                // monotone ticket
    }
    __syncthreads();

    if (s_last) {
        __threadfence();
        double s = 0.0; int c = 0;
        if (tid < SBLK) { s = g_bsum[tid]; c = g_bcnt[tid]; }
        s_rd[tid] = s; s_ri[tid] = c;
        __syncthreads();
        #pragma unroll
        for (int o = QB / 2; o > 0; o >>= 1) {
            if (tid < o) { s_rd[tid] += s_rd[tid + o]; s_ri[tid] += s_ri[tid + o]; }
            __syncthreads();
        }
        if (tid == 0)
            out[0] = (float)(sqrt(s_rd[0]) / (double)s_ri[0]);
    }
}

// ============================================================
extern "C" void kernel_launch(void* const* d_in, const int* in_sizes, int n_in,
                              void* d_out, int out_size) {
    const float* new_xyz = (const float*)d_in[0];
    const float* xyz     = (const float*)d_in[1];
    const float* gt_sdf  = (const float*)d_in[2];

    CMat C;
    {
        const double EP = 0.21, VP = 0.4;
        double A[3][3] = {{1.0/EP, -VP/EP, -VP/EP},
                          {-VP/EP, 1.0/EP, -VP/EP},
                          {-VP,    -VP,    1.0/EP}};
        double det = A[0][0]*(A[1][1]*A[2][2]-A[1][2]*A[2][1])
                   - A[0][1]*(A[1][0]*A[2][2]-A[1][2]*A[2][0])
                   + A[0][2]*(A[1][0]*A[2][1]-A[1][1]*A[2][0]);
        double inv[3][3];
        inv[0][0] = (A[1][1]*A[2][2]-A[1][2]*A[2][1])/det;
        inv[0][1] = (A[0][2]*A[2][1]-A[0][1]*A[2][2])/det;
        inv[0][2] = (A[0][1]*A[1][2]-A[0][2]*A[1][1])/det;
        inv[1][0] = (A[1][2]*A[2][0]-A[1][0]*A[2][2])/det;
        inv[1][1] = (A[0][0]*A[2][2]-A[0][2]*A[2][0])/det;
        inv[1][2] = (A[0][2]*A[1][0]-A[0][0]*A[1][2])/det;
        inv[2][0] = (A[1][0]*A[2][1]-A[1][1]*A[2][0])/det;
        inv[2][1] = (A[0][1]*A[2][0]-A[0][0]*A[2][1])/det;
        inv[2][2] = (A[0][0]*A[1][1]-A[0][1]*A[1][0])/det;
        for (int i = 0; i < 3; i++)
            for (int j = 0; j < 3; j++)
                C.m[i * 3 + j] = (float)inv[i][j];
        C.s = (float)(EP / (2.0 * (1.0 + VP)));
    }

    k_all<<<NB, QB>>>(new_xyz, xyz, gt_sdf, C, (float*)d_out);
}